// round 1
// baseline (speedup 1.0000x reference)
#include <cuda_runtime.h>

// Problem constants (fixed by setup_inputs)
#define MAXN 100000
#define MAXG 64

// Scratch (no allocs allowed) — 16B aligned for vector RED/LDG.128
__device__ __align__(128) float g_dinv[MAXN];
__device__ __align__(128) float g_h[MAXN * 64];
__device__ __align__(128) float g_a[MAXN * 64];
__device__ __align__(128) float g_sums[MAXG * 32];
__device__ __align__(128) float g_cnt[MAXG];

// ---------------------------------------------------------------------------
// Vectorized global reduction (sm_90+): 4 floats, one instruction, no return.
__device__ __forceinline__ void red_add_v4(float* a, float4 v) {
    asm volatile("red.global.add.v4.f32 [%0], {%1,%2,%3,%4};"
                 :: "l"(a), "f"(v.x), "f"(v.y), "f"(v.z), "f"(v.w)
                 : "memory");
}

// ---------------------------------------------------------------------------
// 1) init: dinv = 1 (self loop), zero pool accumulators
__global__ void k_init(float* dinv, float* sums, float* cnt, int N, int G) {
    int i = blockIdx.x * blockDim.x + threadIdx.x;
    if (i < N) dinv[i] = 1.0f;
    if (i < G * 32) sums[i] = 0.0f;
    if (i < G) cnt[i] = 0.0f;
}

// 2) in-degree count (scatter +1 on dst)
__global__ void k_deg(const int* __restrict__ dst, float* dinv, int E) {
    int e = blockIdx.x * blockDim.x + threadIdx.x;
    if (e < E) atomicAdd(&dinv[dst[e]], 1.0f);
}

// 3) dinv = rsqrt(deg)
__global__ void k_rsqrt(float* dinv, int N) {
    int i = blockIdx.x * blockDim.x + threadIdx.x;
    if (i < N) dinv[i] = rsqrtf(dinv[i]);
}

// ---------------------------------------------------------------------------
// GEMM: out[N,Fo] = in[N,Fi] @ W[Fi,Fo], optional relu on input load.
template <int Fi, int Fo, bool RELU>
__global__ void k_gemm(const float* __restrict__ in, const float* __restrict__ W,
                       float* __restrict__ out, int N) {
    constexpr int ROWS = 256 / Fo;
    __shared__ float sW[Fi * Fo];
    __shared__ float sX[ROWS][Fi];

    for (int i = threadIdx.x; i < Fi * Fo; i += 256) sW[i] = W[i];

    int r0 = blockIdx.x * ROWS;
    for (int i = threadIdx.x; i < ROWS * Fi; i += 256) {
        int r = i / Fi, k = i % Fi;
        int gr = r0 + r;
        float v = (gr < N) ? in[(size_t)gr * Fi + k] : 0.0f;
        if (RELU) v = fmaxf(v, 0.0f);
        sX[r][k] = v;
    }
    __syncthreads();

    int col = threadIdx.x % Fo;
    int rr  = threadIdx.x / Fo;
    float acc = 0.0f;
#pragma unroll
    for (int k = 0; k < Fi; k++) acc += sX[rr][k] * sW[k * Fo + col];

    int gr = r0 + rr;
    if (gr < N) out[(size_t)gr * Fo + col] = acc;
}

// ---------------------------------------------------------------------------
// Aggregation init: agg[i,f] = b[f] + h[i,f] * dinv[i]^2   (self loop + bias)
template <int F>
__global__ void k_agginit(float* __restrict__ agg, const float* __restrict__ h,
                          const float* __restrict__ dinv, const float* __restrict__ b,
                          int N) {
    int idx = blockIdx.x * blockDim.x + threadIdx.x;
    if (idx >= N * F) return;
    int i = idx / F, f = idx % F;
    float d = dinv[i];
    agg[idx] = b[f] + h[idx] * d * d;
}

// ---------------------------------------------------------------------------
// Edge scatter: agg[dst] += h[src] * dinv[src]*dinv[dst]
// F/4 lanes cooperate per edge; 16B gather + 16B vector-RED per lane.
template <int F>
__global__ void k_edge(const int* __restrict__ src, const int* __restrict__ dst,
                       const float* __restrict__ h, const float* __restrict__ dinv,
                       float* __restrict__ agg, int E) {
    constexpr int L = F / 4;
    int gid = blockIdx.x * blockDim.x + threadIdx.x;
    int e = gid / L;
    int l = gid % L;
    if (e >= E) return;
    int s = src[e], d = dst[e];
    float w = dinv[s] * dinv[d];
    float4 v = *reinterpret_cast<const float4*>(h + (size_t)s * F + l * 4);
    v.x *= w; v.y *= w; v.z *= w; v.w *= w;
    red_add_v4(agg + (size_t)d * F + l * 4, v);
}

// ---------------------------------------------------------------------------
// Pool: smem binning per block (batch is sorted -> low contention), then flush.
#define POOL_NODES 512
__global__ void k_pool(const float* __restrict__ h, const int* __restrict__ batch,
                       float* __restrict__ sums, float* __restrict__ cnt,
                       int N, int G) {
    __shared__ float sS[MAXG * 32];
    __shared__ float sC[MAXG];
    for (int i = threadIdx.x; i < G * 32; i += 256) sS[i] = 0.0f;
    for (int i = threadIdx.x; i < G; i += 256) sC[i] = 0.0f;
    __syncthreads();

    int f = threadIdx.x % 32;        // lane = feature (conflict-free within warp)
    int w = threadIdx.x / 32;        // warp id = node stripe
    int start = blockIdx.x * POOL_NODES;
    int end = min(start + POOL_NODES, N);
    for (int n = start + w; n < end; n += 8) {
        int g = batch[n];
        atomicAdd(&sS[g * 32 + f], h[(size_t)n * 32 + f]);
        if (f == 0) atomicAdd(&sC[g], 1.0f);
    }
    __syncthreads();

    for (int i = threadIdx.x; i < G * 32; i += 256)
        if (sS[i] != 0.0f) atomicAdd(&sums[i], sS[i]);
    for (int i = threadIdx.x; i < G; i += 256)
        if (sC[i] != 0.0f) atomicAdd(&cnt[i], sC[i]);
}

__global__ void k_final(const float* __restrict__ sums, const float* __restrict__ cnt,
                        float* __restrict__ out, int G) {
    int i = blockIdx.x * blockDim.x + threadIdx.x;
    if (i < G * 32) out[i] = sums[i] / fmaxf(cnt[i / 32], 1.0f);
}

// ---------------------------------------------------------------------------
extern "C" void kernel_launch(void* const* d_in, const int* in_sizes, int n_in,
                              void* d_out, int out_size) {
    const float* x     = (const float*)d_in[0];
    const int*   ei    = (const int*)d_in[1];
    const int*   batch = (const int*)d_in[2];

    // Hedge: num_graphs scalar may or may not be materialized as an input.
    int wi = (n_in >= 10) ? 3 : 2;  // index before W1
    const float* W1 = (const float*)d_in[wi + 1];
    const float* b1 = (const float*)d_in[wi + 2];
    const float* W2 = (const float*)d_in[wi + 3];
    const float* b2 = (const float*)d_in[wi + 4];
    const float* W3 = (const float*)d_in[wi + 5];
    const float* b3 = (const float*)d_in[wi + 6];

    int N = in_sizes[0] / 64;
    int E = in_sizes[1] / 2;
    int G = out_size / 32;
    const int* src = ei;
    const int* dst = ei + E;

    float *p_dinv, *p_h, *p_a, *p_sums, *p_cnt;
    cudaGetSymbolAddress((void**)&p_dinv, g_dinv);
    cudaGetSymbolAddress((void**)&p_h,    g_h);
    cudaGetSymbolAddress((void**)&p_a,    g_a);
    cudaGetSymbolAddress((void**)&p_sums, g_sums);
    cudaGetSymbolAddress((void**)&p_cnt,  g_cnt);

    float* out = (float*)d_out;

    const int T = 256;
    // norm
    k_init<<<(N + T - 1) / T, T>>>(p_dinv, p_sums, p_cnt, N, G);
    k_deg<<<(E + T - 1) / T, T>>>(dst, p_dinv, E);
    k_rsqrt<<<(N + T - 1) / T, T>>>(p_dinv, N);

    // Layer 1: x[N,64] @ W1 -> h ; agg with relu deferred to next gemm's load
    k_gemm<64, 64, false><<<(N + 3) / 4, T>>>(x, W1, p_h, N);
    k_agginit<64><<<(N * 64 + T - 1) / T, T>>>(p_a, p_h, p_dinv, b1, N);
    k_edge<64><<<((size_t)E * 16 + T - 1) / T, T>>>(src, dst, p_h, p_dinv, p_a, E);

    // Layer 2: relu(a) @ W2
    k_gemm<64, 64, true><<<(N + 3) / 4, T>>>(p_a, W2, p_h, N);
    k_agginit<64><<<(N * 64 + T - 1) / T, T>>>(p_a, p_h, p_dinv, b2, N);
    k_edge<64><<<((size_t)E * 16 + T - 1) / T, T>>>(src, dst, p_h, p_dinv, p_a, E);

    // Layer 3: a @ W3 -> [N,32]
    k_gemm<64, 32, false><<<(N + 7) / 8, T>>>(p_a, W3, p_h, N);
    k_agginit<32><<<(N * 32 + T - 1) / T, T>>>(p_a, p_h, p_dinv, b3, N);
    k_edge<32><<<((size_t)E * 8 + T - 1) / T, T>>>(src, dst, p_h, p_dinv, p_a, E);

    // Global mean pool
    k_pool<<<(N + POOL_NODES - 1) / POOL_NODES, T>>>(p_a, batch, p_sums, p_cnt, N, G);
    k_final<<<(G * 32 + T - 1) / T, T>>>(p_sums, p_cnt, out, G);
}

// round 2
// speedup vs baseline: 1.6451x; 1.6451x over previous
#include <cuda_runtime.h>

#define MAXN 100000
#define MAXG 64

__device__ __align__(128) float g_dinv[MAXN];
__device__ __align__(128) float g_h[MAXN * 64];
__device__ __align__(128) float g_a[MAXN * 64];
__device__ __align__(128) float g_sums[MAXG * 32];
__device__ __align__(128) float g_cnt[MAXG];

// Vectorized global reduction (sm_90+): 4 floats, one instruction, no return.
__device__ __forceinline__ void red_add_v4(float* a, float4 v) {
    asm volatile("red.global.add.v4.f32 [%0], {%1,%2,%3,%4};"
                 :: "l"(a), "f"(v.x), "f"(v.y), "f"(v.z), "f"(v.w)
                 : "memory");
}

// ---------------------------------------------------------------------------
__global__ void k_init(float* dinv, float* sums, float* cnt, int N, int G) {
    int i = blockIdx.x * blockDim.x + threadIdx.x;
    if (i < N) dinv[i] = 1.0f;
    if (i < G * 32) sums[i] = 0.0f;
    if (i < G) cnt[i] = 0.0f;
}

__global__ void k_deg(const int* __restrict__ dst, float* dinv, int E) {
    int e = blockIdx.x * blockDim.x + threadIdx.x;
    if (e < E) atomicAdd(&dinv[dst[e]], 1.0f);
}

__global__ void k_rsqrt(float* dinv, int N) {
    int i = blockIdx.x * blockDim.x + threadIdx.x;
    if (i < N) dinv[i] = rsqrtf(dinv[i]);
}

// ---------------------------------------------------------------------------
// Register-blocked GEMM fused with aggregation-init epilogue.
//   h[N,Fo]   = act(in)[N,64] @ W[64,Fo]
//   a[N,Fo]   = bias + h * dinv^2          (self-loop + bias)
// Each thread computes a 4x4 output block: per k-step 4 scalar LDS (broadcast)
// + 1 LDS.128 + 16 FFMA  -> FMA-issue bound.
template <int Fo, bool RELU>
__global__ __launch_bounds__(256) void k_gemm_fused(
    const float* __restrict__ in, const float* __restrict__ W,
    const float* __restrict__ bias, const float* __restrict__ dinv,
    float* __restrict__ h, float* __restrict__ a, int N) {

    constexpr int CG = Fo / 4;      // column groups (threads along cols)
    constexpr int RG = 256 / CG;    // row groups
    constexpr int RB = RG * 4;      // rows per block

    __shared__ float sX[RB * 64];
    __shared__ float sW[64 * Fo];

    int tid = threadIdx.x;

    // W tile: 64*Fo contiguous floats
    for (int i = tid * 4; i < 64 * Fo; i += 1024)
        *(float4*)(sW + i) = *(const float4*)(W + i);

    // X tile: rows are dense (pitch 64 floats) -> contiguous copy
    int r0 = blockIdx.x * RB;
    int nrow = min(RB, N - r0);
    int nflt = nrow * 64;
    const float* gin = in + (size_t)r0 * 64;
    for (int i = tid * 4; i < nflt; i += 1024) {
        float4 v = *(const float4*)(gin + i);
        if (RELU) {
            v.x = fmaxf(v.x, 0.0f); v.y = fmaxf(v.y, 0.0f);
            v.z = fmaxf(v.z, 0.0f); v.w = fmaxf(v.w, 0.0f);
        }
        *(float4*)(sX + i) = v;
    }
    __syncthreads();

    int cx = tid % CG;
    int ry = tid / CG;

    float acc[4][4] = {};
    const float* xs = sX + ry * 4 * 64;
    const float* ws = sW + cx * 4;

#pragma unroll 8
    for (int k = 0; k < 64; k++) {
        float4 wv = *(const float4*)(ws + k * Fo);
        float x0 = xs[k];
        float x1 = xs[64 + k];
        float x2 = xs[128 + k];
        float x3 = xs[192 + k];
        acc[0][0] += x0 * wv.x; acc[0][1] += x0 * wv.y; acc[0][2] += x0 * wv.z; acc[0][3] += x0 * wv.w;
        acc[1][0] += x1 * wv.x; acc[1][1] += x1 * wv.y; acc[1][2] += x1 * wv.z; acc[1][3] += x1 * wv.w;
        acc[2][0] += x2 * wv.x; acc[2][1] += x2 * wv.y; acc[2][2] += x2 * wv.z; acc[2][3] += x2 * wv.w;
        acc[3][0] += x3 * wv.x; acc[3][1] += x3 * wv.y; acc[3][2] += x3 * wv.z; acc[3][3] += x3 * wv.w;
    }

    float4 bv = *(const float4*)(bias + cx * 4);
#pragma unroll
    for (int i = 0; i < 4; i++) {
        int gr = r0 + ry * 4 + i;
        if (gr < N) {
            float d = dinv[gr];
            float d2 = d * d;
            float4 hv = make_float4(acc[i][0], acc[i][1], acc[i][2], acc[i][3]);
            *(float4*)(h + (size_t)gr * Fo + cx * 4) = hv;
            float4 av = make_float4(bv.x + hv.x * d2, bv.y + hv.y * d2,
                                    bv.z + hv.z * d2, bv.w + hv.w * d2);
            *(float4*)(a + (size_t)gr * Fo + cx * 4) = av;
        }
    }
}

// ---------------------------------------------------------------------------
// Edge scatter: agg[dst] += h[src] * dinv[src]*dinv[dst]
// F/4 lanes per edge: 16B coalesced gather + 16B vector-RED per lane.
// Index loads are same-address within the lane group -> broadcast, no waste.
template <int F>
__global__ void k_edge(const int* __restrict__ src, const int* __restrict__ dst,
                       const float* __restrict__ h, const float* __restrict__ dinv,
                       float* __restrict__ agg, int E) {
    constexpr int L = F / 4;
    int gid = blockIdx.x * blockDim.x + threadIdx.x;
    int e = gid / L;
    int l = gid % L;
    if (e >= E) return;
    int s = src[e], d = dst[e];
    float w = dinv[s] * dinv[d];
    float4 v = *reinterpret_cast<const float4*>(h + (size_t)s * F + l * 4);
    v.x *= w; v.y *= w; v.z *= w; v.w *= w;
    red_add_v4(agg + (size_t)d * F + l * 4, v);
}

// ---------------------------------------------------------------------------
#define POOL_NODES 512
__global__ void k_pool(const float* __restrict__ h, const int* __restrict__ batch,
                       float* __restrict__ sums, float* __restrict__ cnt,
                       int N, int G) {
    __shared__ float sS[MAXG * 32];
    __shared__ float sC[MAXG];
    for (int i = threadIdx.x; i < G * 32; i += 256) sS[i] = 0.0f;
    for (int i = threadIdx.x; i < G; i += 256) sC[i] = 0.0f;
    __syncthreads();

    int f = threadIdx.x % 32;
    int w = threadIdx.x / 32;
    int start = blockIdx.x * POOL_NODES;
    int end = min(start + POOL_NODES, N);
    for (int n = start + w; n < end; n += 8) {
        int g = batch[n];
        atomicAdd(&sS[g * 32 + f], h[(size_t)n * 32 + f]);
        if (f == 0) atomicAdd(&sC[g], 1.0f);
    }
    __syncthreads();

    for (int i = threadIdx.x; i < G * 32; i += 256)
        if (sS[i] != 0.0f) atomicAdd(&sums[i], sS[i]);
    for (int i = threadIdx.x; i < G; i += 256)
        if (sC[i] != 0.0f) atomicAdd(&cnt[i], sC[i]);
}

__global__ void k_final(const float* __restrict__ sums, const float* __restrict__ cnt,
                        float* __restrict__ out, int G) {
    int i = blockIdx.x * blockDim.x + threadIdx.x;
    if (i < G * 32) out[i] = sums[i] / fmaxf(cnt[i / 32], 1.0f);
}

// ---------------------------------------------------------------------------
extern "C" void kernel_launch(void* const* d_in, const int* in_sizes, int n_in,
                              void* d_out, int out_size) {
    const float* x     = (const float*)d_in[0];
    const int*   ei    = (const int*)d_in[1];
    const int*   batch = (const int*)d_in[2];

    int wi = (n_in >= 10) ? 3 : 2;
    const float* W1 = (const float*)d_in[wi + 1];
    const float* b1 = (const float*)d_in[wi + 2];
    const float* W2 = (const float*)d_in[wi + 3];
    const float* b2 = (const float*)d_in[wi + 4];
    const float* W3 = (const float*)d_in[wi + 5];
    const float* b3 = (const float*)d_in[wi + 6];

    int N = in_sizes[0] / 64;
    int E = in_sizes[1] / 2;
    int G = out_size / 32;
    const int* src = ei;
    const int* dst = ei + E;

    float *p_dinv, *p_h, *p_a, *p_sums, *p_cnt;
    cudaGetSymbolAddress((void**)&p_dinv, g_dinv);
    cudaGetSymbolAddress((void**)&p_h,    g_h);
    cudaGetSymbolAddress((void**)&p_a,    g_a);
    cudaGetSymbolAddress((void**)&p_sums, g_sums);
    cudaGetSymbolAddress((void**)&p_cnt,  g_cnt);

    float* out = (float*)d_out;
    const int T = 256;

    // Normalization
    k_init<<<(N + T - 1) / T, T>>>(p_dinv, p_sums, p_cnt, N, G);
    k_deg<<<(E + T - 1) / T, T>>>(dst, p_dinv, E);
    k_rsqrt<<<(N + T - 1) / T, T>>>(p_dinv, N);

    // Layer 1: h1 = x@W1 ; a1 = b1 + h1*d^2 ; a1 += edges
    k_gemm_fused<64, false><<<(N + 63) / 64, T>>>(x, W1, b1, p_dinv, p_h, p_a, N);
    k_edge<64><<<((size_t)E * 16 + T - 1) / T, T>>>(src, dst, p_h, p_dinv, p_a, E);

    // Layer 2: h2 = relu(a1)@W2 ; a2 = b2 + h2*d^2 ; a2 += edges
    k_gemm_fused<64, true><<<(N + 63) / 64, T>>>(p_a, W2, b2, p_dinv, p_h, p_a, N);
    k_edge<64><<<((size_t)E * 16 + T - 1) / T, T>>>(src, dst, p_h, p_dinv, p_a, E);

    // Layer 3: h3 = a2@W3 ; a3 = b3 + h3*d^2 ; a3 += edges
    k_gemm_fused<32, false><<<(N + 127) / 128, T>>>(p_a, W3, b3, p_dinv, p_h, p_a, N);
    k_edge<32><<<((size_t)E * 8 + T - 1) / T, T>>>(src, dst, p_h, p_dinv, p_a, E);

    // Global mean pool
    k_pool<<<(N + POOL_NODES - 1) / POOL_NODES, T>>>(p_a, batch, p_sums, p_cnt, N, G);
    k_final<<<(G * 32 + T - 1) / T, T>>>(p_sums, p_cnt, out, G);
}

// round 3
// speedup vs baseline: 2.2040x; 1.3398x over previous
#include <cuda_runtime.h>

#define MAXN 100000
#define MAXE 1600000
#define MAXG 64

__device__ __align__(128) float g_dinv[MAXN];
__device__ __align__(128) int   g_deg[MAXN];
__device__ __align__(128) int   g_rowptr[MAXN];
__device__ __align__(128) int   g_cursor[MAXN];
__device__ __align__(128) int   g_aux[128];
__device__ __align__(128) int2  g_edat[MAXE];   // packed (src, weight-bits)
__device__ __align__(128) float g_h[MAXN * 64];
__device__ __align__(128) float g_a[MAXN * 64];
__device__ __align__(128) float g_sums[MAXG * 32];
__device__ __align__(128) float g_cnt[MAXG];

// ---------------------------------------------------------------------------
__global__ void k_zero(int* deg, float* sums, float* cnt, int N, int G) {
    int i = blockIdx.x * blockDim.x + threadIdx.x;
    if (i < N) deg[i] = 0;
    if (i < G * 32) sums[i] = 0.0f;
    if (i < G) cnt[i] = 0.0f;
}

__global__ void k_hist(const int* __restrict__ dst, int* deg, int E) {
    int e = blockIdx.x * blockDim.x + threadIdx.x;
    if (e < E) atomicAdd(&deg[dst[e]], 1);
}

__global__ void k_dinv(const int* __restrict__ deg, float* dinv, int N) {
    int i = blockIdx.x * blockDim.x + threadIdx.x;
    if (i < N) dinv[i] = rsqrtf((float)deg[i] + 1.0f);  // +1 self loop
}

// --- exclusive scan of deg -> rowptr (3 kernels, N <= 128*1024) -------------
__global__ void k_scan1(const int* __restrict__ deg, int* rowptr, int* aux, int N) {
    __shared__ int s[1024];
    int i = blockIdx.x * 1024 + threadIdx.x;
    int v = (i < N) ? deg[i] : 0;
    s[threadIdx.x] = v;
    __syncthreads();
    for (int off = 1; off < 1024; off <<= 1) {
        int t = (threadIdx.x >= off) ? s[threadIdx.x - off] : 0;
        __syncthreads();
        s[threadIdx.x] += t;
        __syncthreads();
    }
    if (i < N) rowptr[i] = s[threadIdx.x] - v;          // exclusive within block
    if (threadIdx.x == 1023) aux[blockIdx.x] = s[1023]; // block total
}

__global__ void k_scan2(int* aux, int nb) {
    __shared__ int s[128];
    int v = (threadIdx.x < nb) ? aux[threadIdx.x] : 0;
    s[threadIdx.x] = v;
    __syncthreads();
    for (int off = 1; off < 128; off <<= 1) {
        int t = (threadIdx.x >= off) ? s[threadIdx.x - off] : 0;
        __syncthreads();
        s[threadIdx.x] += t;
        __syncthreads();
    }
    if (threadIdx.x < nb) aux[threadIdx.x] = s[threadIdx.x] - v;  // exclusive
}

__global__ void k_scan3(int* rowptr, int* cursor, const int* __restrict__ aux, int N) {
    int i = blockIdx.x * blockDim.x + threadIdx.x;
    if (i < N) {
        int r = rowptr[i] + aux[i >> 10];
        rowptr[i] = r;
        cursor[i] = r;
    }
}

// --- scatter edges into CSC slots, weight precomputed -----------------------
__global__ void k_scatter(const int* __restrict__ src, const int* __restrict__ dst,
                          const float* __restrict__ dinv, int* cursor,
                          int2* edat, int E) {
    int e = blockIdx.x * blockDim.x + threadIdx.x;
    if (e >= E) return;
    int s = src[e], d = dst[e];
    int pos = atomicAdd(&cursor[d], 1);
    float w = dinv[s] * dinv[d];
    edat[pos] = make_int2(s, __float_as_int(w));
}

// ---------------------------------------------------------------------------
// Register-blocked GEMM: h[N,Fo] = act(in)[N,64] @ W[64,Fo]
template <int Fo, bool RELU>
__global__ __launch_bounds__(256) void k_gemm(
    const float* __restrict__ in, const float* __restrict__ W,
    float* __restrict__ h, int N) {

    constexpr int CG = Fo / 4;
    constexpr int RG = 256 / CG;
    constexpr int RB = RG * 4;

    __shared__ float sX[RB * 64];
    __shared__ float sW[64 * Fo];

    int tid = threadIdx.x;
    for (int i = tid * 4; i < 64 * Fo; i += 1024)
        *(float4*)(sW + i) = *(const float4*)(W + i);

    int r0 = blockIdx.x * RB;
    int nrow = min(RB, N - r0);
    int nflt = nrow * 64;
    const float* gin = in + (size_t)r0 * 64;
    for (int i = tid * 4; i < nflt; i += 1024) {
        float4 v = *(const float4*)(gin + i);
        if (RELU) {
            v.x = fmaxf(v.x, 0.0f); v.y = fmaxf(v.y, 0.0f);
            v.z = fmaxf(v.z, 0.0f); v.w = fmaxf(v.w, 0.0f);
        }
        *(float4*)(sX + i) = v;
    }
    __syncthreads();

    int cx = tid % CG;
    int ry = tid / CG;

    float acc[4][4] = {};
    const float* xs = sX + ry * 4 * 64;
    const float* ws = sW + cx * 4;

#pragma unroll 8
    for (int k = 0; k < 64; k++) {
        float4 wv = *(const float4*)(ws + k * Fo);
        float x0 = xs[k];
        float x1 = xs[64 + k];
        float x2 = xs[128 + k];
        float x3 = xs[192 + k];
        acc[0][0] += x0 * wv.x; acc[0][1] += x0 * wv.y; acc[0][2] += x0 * wv.z; acc[0][3] += x0 * wv.w;
        acc[1][0] += x1 * wv.x; acc[1][1] += x1 * wv.y; acc[1][2] += x1 * wv.z; acc[1][3] += x1 * wv.w;
        acc[2][0] += x2 * wv.x; acc[2][1] += x2 * wv.y; acc[2][2] += x2 * wv.z; acc[2][3] += x2 * wv.w;
        acc[3][0] += x3 * wv.x; acc[3][1] += x3 * wv.y; acc[3][2] += x3 * wv.z; acc[3][3] += x3 * wv.w;
    }

#pragma unroll
    for (int i = 0; i < 4; i++) {
        int gr = r0 + ry * 4 + i;
        if (gr < N)
            *(float4*)(h + (size_t)gr * Fo + cx * 4) =
                make_float4(acc[i][0], acc[i][1], acc[i][2], acc[i][3]);
    }
}

// ---------------------------------------------------------------------------
// Gather-aggregate (CSC): out[i] = bias + h[i]*dinv[i]^2 + sum_j w_j * h[src_j]
// F/4 lanes per node; gathers unrolled x4 for MLP. No atomics.
template <int F>
__global__ __launch_bounds__(256) void k_agg(
    const float* __restrict__ h, const int2* __restrict__ edat,
    const int* __restrict__ rowptr, const int* __restrict__ deg,
    const float* __restrict__ dinv, const float* __restrict__ bias,
    float* __restrict__ out, int N) {

    constexpr int L = F / 4;
    int gid = blockIdx.x * blockDim.x + threadIdx.x;
    int node = gid / L;
    int l = gid % L;
    if (node >= N) return;

    int beg = rowptr[node];
    int cnt = deg[node];

    float4 a0 = make_float4(0.f, 0.f, 0.f, 0.f);
    float4 a1 = make_float4(0.f, 0.f, 0.f, 0.f);

    int j = 0;
    for (; j + 3 < cnt; j += 4) {
        int2 e0 = edat[beg + j];
        int2 e1 = edat[beg + j + 1];
        int2 e2 = edat[beg + j + 2];
        int2 e3 = edat[beg + j + 3];
        float4 v0 = *(const float4*)(h + (size_t)e0.x * F + l * 4);
        float4 v1 = *(const float4*)(h + (size_t)e1.x * F + l * 4);
        float4 v2 = *(const float4*)(h + (size_t)e2.x * F + l * 4);
        float4 v3 = *(const float4*)(h + (size_t)e3.x * F + l * 4);
        float w0 = __int_as_float(e0.y), w1 = __int_as_float(e1.y);
        float w2 = __int_as_float(e2.y), w3 = __int_as_float(e3.y);
        a0.x += v0.x * w0; a0.y += v0.y * w0; a0.z += v0.z * w0; a0.w += v0.w * w0;
        a1.x += v1.x * w1; a1.y += v1.y * w1; a1.z += v1.z * w1; a1.w += v1.w * w1;
        a0.x += v2.x * w2; a0.y += v2.y * w2; a0.z += v2.z * w2; a0.w += v2.w * w2;
        a1.x += v3.x * w3; a1.y += v3.y * w3; a1.z += v3.z * w3; a1.w += v3.w * w3;
    }
    for (; j < cnt; j++) {
        int2 e = edat[beg + j];
        float4 v = *(const float4*)(h + (size_t)e.x * F + l * 4);
        float w = __int_as_float(e.y);
        a0.x += v.x * w; a0.y += v.y * w; a0.z += v.z * w; a0.w += v.w * w;
    }

    float d = dinv[node];
    float d2 = d * d;
    float4 hv = *(const float4*)(h + (size_t)node * F + l * 4);
    float4 bv = *(const float4*)(bias + l * 4);
    float4 o;
    o.x = bv.x + hv.x * d2 + a0.x + a1.x;
    o.y = bv.y + hv.y * d2 + a0.y + a1.y;
    o.z = bv.z + hv.z * d2 + a0.z + a1.z;
    o.w = bv.w + hv.w * d2 + a0.w + a1.w;
    *(float4*)(out + (size_t)node * F + l * 4) = o;
}

// ---------------------------------------------------------------------------
#define POOL_NODES 512
__global__ void k_pool(const float* __restrict__ h, const int* __restrict__ batch,
                       float* __restrict__ sums, float* __restrict__ cnt,
                       int N, int G) {
    __shared__ float sS[MAXG * 32];
    __shared__ float sC[MAXG];
    for (int i = threadIdx.x; i < G * 32; i += 256) sS[i] = 0.0f;
    for (int i = threadIdx.x; i < G; i += 256) sC[i] = 0.0f;
    __syncthreads();

    int f = threadIdx.x % 32;
    int w = threadIdx.x / 32;
    int start = blockIdx.x * POOL_NODES;
    int end = min(start + POOL_NODES, N);
    for (int n = start + w; n < end; n += 8) {
        int g = batch[n];
        atomicAdd(&sS[g * 32 + f], h[(size_t)n * 32 + f]);
        if (f == 0) atomicAdd(&sC[g], 1.0f);
    }
    __syncthreads();

    for (int i = threadIdx.x; i < G * 32; i += 256)
        if (sS[i] != 0.0f) atomicAdd(&sums[i], sS[i]);
    for (int i = threadIdx.x; i < G; i += 256)
        if (sC[i] != 0.0f) atomicAdd(&cnt[i], sC[i]);
}

__global__ void k_final(const float* __restrict__ sums, const float* __restrict__ cnt,
                        float* __restrict__ out, int G) {
    int i = blockIdx.x * blockDim.x + threadIdx.x;
    if (i < G * 32) out[i] = sums[i] / fmaxf(cnt[i / 32], 1.0f);
}

// ---------------------------------------------------------------------------
extern "C" void kernel_launch(void* const* d_in, const int* in_sizes, int n_in,
                              void* d_out, int out_size) {
    const float* x     = (const float*)d_in[0];
    const int*   ei    = (const int*)d_in[1];
    const int*   batch = (const int*)d_in[2];

    int wi = (n_in >= 10) ? 3 : 2;
    const float* W1 = (const float*)d_in[wi + 1];
    const float* b1 = (const float*)d_in[wi + 2];
    const float* W2 = (const float*)d_in[wi + 3];
    const float* b2 = (const float*)d_in[wi + 4];
    const float* W3 = (const float*)d_in[wi + 5];
    const float* b3 = (const float*)d_in[wi + 6];

    int N = in_sizes[0] / 64;
    int E = in_sizes[1] / 2;
    int G = out_size / 32;
    const int* src = ei;
    const int* dst = ei + E;

    float *p_dinv, *p_h, *p_a, *p_sums, *p_cnt;
    int *p_deg, *p_rowptr, *p_cursor, *p_aux;
    int2 *p_edat;
    cudaGetSymbolAddress((void**)&p_dinv,   g_dinv);
    cudaGetSymbolAddress((void**)&p_deg,    g_deg);
    cudaGetSymbolAddress((void**)&p_rowptr, g_rowptr);
    cudaGetSymbolAddress((void**)&p_cursor, g_cursor);
    cudaGetSymbolAddress((void**)&p_aux,    g_aux);
    cudaGetSymbolAddress((void**)&p_edat,   g_edat);
    cudaGetSymbolAddress((void**)&p_h,      g_h);
    cudaGetSymbolAddress((void**)&p_a,      g_a);
    cudaGetSymbolAddress((void**)&p_sums,   g_sums);
    cudaGetSymbolAddress((void**)&p_cnt,    g_cnt);

    float* out = (float*)d_out;
    const int T = 256;
    int nb_scan = (N + 1023) / 1024;

    // --- build CSC + norms ---
    k_zero<<<(N + T - 1) / T, T>>>(p_deg, p_sums, p_cnt, N, G);
    k_hist<<<(E + T - 1) / T, T>>>(dst, p_deg, E);
    k_dinv<<<(N + T - 1) / T, T>>>(p_deg, p_dinv, N);
    k_scan1<<<nb_scan, 1024>>>(p_deg, p_rowptr, p_aux, N);
    k_scan2<<<1, 128>>>(p_aux, nb_scan);
    k_scan3<<<(N + T - 1) / T, T>>>(p_rowptr, p_cursor, p_aux, N);
    k_scatter<<<(E + T - 1) / T, T>>>(src, dst, p_dinv, p_cursor, p_edat, E);

    // --- layer 1 ---
    k_gemm<64, false><<<(N + 63) / 64, T>>>(x, W1, p_h, N);
    k_agg<64><<<((size_t)N * 16 + T - 1) / T, T>>>(p_h, p_edat, p_rowptr, p_deg,
                                                   p_dinv, b1, p_a, N);
    // --- layer 2 ---
    k_gemm<64, true><<<(N + 63) / 64, T>>>(p_a, W2, p_h, N);
    k_agg<64><<<((size_t)N * 16 + T - 1) / T, T>>>(p_h, p_edat, p_rowptr, p_deg,
                                                   p_dinv, b2, p_a, N);
    // --- layer 3 ---
    k_gemm<32, false><<<(N + 127) / 128, T>>>(p_a, W3, p_h, N);
    k_agg<32><<<((size_t)N * 8 + T - 1) / T, T>>>(p_h, p_edat, p_rowptr, p_deg,
                                                  p_dinv, b3, p_a, N);

    // --- pool ---
    k_pool<<<(N + POOL_NODES - 1) / POOL_NODES, T>>>(p_a, batch, p_sums, p_cnt, N, G);
    k_final<<<(G * 32 + T - 1) / T, T>>>(p_sums, p_cnt, out, G);
}

// round 4
// speedup vs baseline: 2.4827x; 1.1264x over previous
#include <cuda_runtime.h>
#include <cuda_fp16.h>

#define MAXN 100000
#define MAXE 1600000
#define MAXG 64

__device__ __align__(128) float  g_dinv[MAXN];
__device__ __align__(128) int    g_deg[MAXN];
__device__ __align__(128) int    g_rowptr[MAXN];
__device__ __align__(128) int    g_cursor[MAXN];
__device__ __align__(128) int    g_aux[128];
__device__ __align__(128) int2   g_edat[MAXE];      // packed (src, weight-bits)
__device__ __align__(128) __half g_h[MAXN * 64];    // fp16 features for gather
__device__ __align__(128) float  g_a[MAXN * 64];
__device__ __align__(128) float  g_sums[MAXG * 32];
__device__ __align__(128) float  g_cnt[MAXG];

// ---------------------------------------------------------------------------
__global__ void k_zero(int* deg, float* sums, float* cnt, int N, int G) {
    int i = blockIdx.x * blockDim.x + threadIdx.x;
    if (i < N) deg[i] = 0;
    if (i < G * 32) sums[i] = 0.0f;
    if (i < G) cnt[i] = 0.0f;
}

__global__ void k_hist(const int* __restrict__ dst, int* deg, int E) {
    int e = blockIdx.x * blockDim.x + threadIdx.x;
    if (e < E) atomicAdd(&deg[dst[e]], 1);
}

__global__ void k_dinv(const int* __restrict__ deg, float* dinv, int N) {
    int i = blockIdx.x * blockDim.x + threadIdx.x;
    if (i < N) dinv[i] = rsqrtf((float)deg[i] + 1.0f);  // +1 self loop
}

// --- exclusive scan of deg -> rowptr ---------------------------------------
__global__ void k_scan1(const int* __restrict__ deg, int* rowptr, int* aux, int N) {
    __shared__ int s[1024];
    int i = blockIdx.x * 1024 + threadIdx.x;
    int v = (i < N) ? deg[i] : 0;
    s[threadIdx.x] = v;
    __syncthreads();
    for (int off = 1; off < 1024; off <<= 1) {
        int t = (threadIdx.x >= off) ? s[threadIdx.x - off] : 0;
        __syncthreads();
        s[threadIdx.x] += t;
        __syncthreads();
    }
    if (i < N) rowptr[i] = s[threadIdx.x] - v;
    if (threadIdx.x == 1023) aux[blockIdx.x] = s[1023];
}

__global__ void k_scan2(int* aux, int nb) {
    __shared__ int s[128];
    int v = (threadIdx.x < nb) ? aux[threadIdx.x] : 0;
    s[threadIdx.x] = v;
    __syncthreads();
    for (int off = 1; off < 128; off <<= 1) {
        int t = (threadIdx.x >= off) ? s[threadIdx.x - off] : 0;
        __syncthreads();
        s[threadIdx.x] += t;
        __syncthreads();
    }
    if (threadIdx.x < nb) aux[threadIdx.x] = s[threadIdx.x] - v;
}

__global__ void k_scan3(int* rowptr, int* cursor, const int* __restrict__ aux, int N) {
    int i = blockIdx.x * blockDim.x + threadIdx.x;
    if (i < N) {
        int r = rowptr[i] + aux[i >> 10];
        rowptr[i] = r;
        cursor[i] = r;
    }
}

__global__ void k_scatter(const int* __restrict__ src, const int* __restrict__ dst,
                          const float* __restrict__ dinv, int* cursor,
                          int2* edat, int E) {
    int e = blockIdx.x * blockDim.x + threadIdx.x;
    if (e >= E) return;
    int s = src[e], d = dst[e];
    int pos = atomicAdd(&cursor[d], 1);
    float w = dinv[s] * dinv[d];
    edat[pos] = make_int2(s, __float_as_int(w));
}

// ---------------------------------------------------------------------------
// Register-blocked GEMM: h[N,Fo](fp16) = act(in)[N,64] @ W[64,Fo]
template <int Fo, bool RELU>
__global__ __launch_bounds__(256) void k_gemm(
    const float* __restrict__ in, const float* __restrict__ W,
    __half* __restrict__ h, int N) {

    constexpr int CG = Fo / 4;
    constexpr int RG = 256 / CG;
    constexpr int RB = RG * 4;

    __shared__ float sX[RB * 64];
    __shared__ float sW[64 * Fo];

    int tid = threadIdx.x;
    for (int i = tid * 4; i < 64 * Fo; i += 1024)
        *(float4*)(sW + i) = *(const float4*)(W + i);

    int r0 = blockIdx.x * RB;
    int nrow = min(RB, N - r0);
    int nflt = nrow * 64;
    const float* gin = in + (size_t)r0 * 64;
    for (int i = tid * 4; i < nflt; i += 1024) {
        float4 v = *(const float4*)(gin + i);
        if (RELU) {
            v.x = fmaxf(v.x, 0.0f); v.y = fmaxf(v.y, 0.0f);
            v.z = fmaxf(v.z, 0.0f); v.w = fmaxf(v.w, 0.0f);
        }
        *(float4*)(sX + i) = v;
    }
    __syncthreads();

    int cx = tid % CG;
    int ry = tid / CG;

    float acc[4][4] = {};
    const float* xs = sX + ry * 4 * 64;
    const float* ws = sW + cx * 4;

#pragma unroll 8
    for (int k = 0; k < 64; k++) {
        float4 wv = *(const float4*)(ws + k * Fo);
        float x0 = xs[k];
        float x1 = xs[64 + k];
        float x2 = xs[128 + k];
        float x3 = xs[192 + k];
        acc[0][0] += x0 * wv.x; acc[0][1] += x0 * wv.y; acc[0][2] += x0 * wv.z; acc[0][3] += x0 * wv.w;
        acc[1][0] += x1 * wv.x; acc[1][1] += x1 * wv.y; acc[1][2] += x1 * wv.z; acc[1][3] += x1 * wv.w;
        acc[2][0] += x2 * wv.x; acc[2][1] += x2 * wv.y; acc[2][2] += x2 * wv.z; acc[2][3] += x2 * wv.w;
        acc[3][0] += x3 * wv.x; acc[3][1] += x3 * wv.y; acc[3][2] += x3 * wv.z; acc[3][3] += x3 * wv.w;
    }

#pragma unroll
    for (int i = 0; i < 4; i++) {
        int gr = r0 + ry * 4 + i;
        if (gr < N) {
            __half2 p0 = __floats2half2_rn(acc[i][0], acc[i][1]);
            __half2 p1 = __floats2half2_rn(acc[i][2], acc[i][3]);
            uint2 pk = make_uint2(*(unsigned*)&p0, *(unsigned*)&p1);
            *(uint2*)(h + (size_t)gr * Fo + cx * 4) = pk;   // 8B store
        }
    }
}

// ---------------------------------------------------------------------------
// Gather-aggregate (CSC, fp16 gather, fp32 accumulate):
//   out[i] = bias + h[i]*dinv[i]^2 + sum_j w_j * h[src_j]
// L = F/8 lanes per node; each lane loads one uint4 (8 halves) per edge.
template <int F>
__global__ __launch_bounds__(256) void k_agg(
    const __half* __restrict__ h, const int2* __restrict__ edat,
    const int* __restrict__ rowptr, const int* __restrict__ deg,
    const float* __restrict__ dinv, const float* __restrict__ bias,
    float* __restrict__ out, int N) {

    constexpr int L = F / 8;
    int gid = blockIdx.x * blockDim.x + threadIdx.x;
    int node = gid / L;
    int l = gid % L;
    if (node >= N) return;

    int beg = rowptr[node];
    int cnt = deg[node];

    float acc[8] = {};

    int j = 0;
    for (; j + 3 < cnt; j += 4) {
        int2 e0 = edat[beg + j];
        int2 e1 = edat[beg + j + 1];
        int2 e2 = edat[beg + j + 2];
        int2 e3 = edat[beg + j + 3];
        uint4 r0 = *(const uint4*)(h + (size_t)e0.x * F + l * 8);
        uint4 r1 = *(const uint4*)(h + (size_t)e1.x * F + l * 8);
        uint4 r2 = *(const uint4*)(h + (size_t)e2.x * F + l * 8);
        uint4 r3 = *(const uint4*)(h + (size_t)e3.x * F + l * 8);
        float w0 = __int_as_float(e0.y), w1 = __int_as_float(e1.y);
        float w2 = __int_as_float(e2.y), w3 = __int_as_float(e3.y);
        const __half2* p0 = (const __half2*)&r0;
        const __half2* p1 = (const __half2*)&r1;
        const __half2* p2 = (const __half2*)&r2;
        const __half2* p3 = (const __half2*)&r3;
#pragma unroll
        for (int q = 0; q < 4; q++) {
            float2 f0 = __half22float2(p0[q]);
            float2 f1 = __half22float2(p1[q]);
            float2 f2 = __half22float2(p2[q]);
            float2 f3 = __half22float2(p3[q]);
            acc[2*q]   += f0.x * w0 + f1.x * w1 + f2.x * w2 + f3.x * w3;
            acc[2*q+1] += f0.y * w0 + f1.y * w1 + f2.y * w2 + f3.y * w3;
        }
    }
    for (; j < cnt; j++) {
        int2 e = edat[beg + j];
        uint4 r = *(const uint4*)(h + (size_t)e.x * F + l * 8);
        float w = __int_as_float(e.y);
        const __half2* p = (const __half2*)&r;
#pragma unroll
        for (int q = 0; q < 4; q++) {
            float2 f = __half22float2(p[q]);
            acc[2*q]   += f.x * w;
            acc[2*q+1] += f.y * w;
        }
    }

    float d = dinv[node];
    float d2 = d * d;
    uint4 rs = *(const uint4*)(h + (size_t)node * F + l * 8);
    const __half2* ps = (const __half2*)&rs;
    float4 b0 = *(const float4*)(bias + l * 8);
    float4 b1 = *(const float4*)(bias + l * 8 + 4);

    float o[8];
#pragma unroll
    for (int q = 0; q < 4; q++) {
        float2 f = __half22float2(ps[q]);
        o[2*q]   = acc[2*q]   + f.x * d2;
        o[2*q+1] = acc[2*q+1] + f.y * d2;
    }
    float4 w0 = make_float4(o[0] + b0.x, o[1] + b0.y, o[2] + b0.z, o[3] + b0.w);
    float4 w1 = make_float4(o[4] + b1.x, o[5] + b1.y, o[6] + b1.z, o[7] + b1.w);
    *(float4*)(out + (size_t)node * F + l * 8)     = w0;
    *(float4*)(out + (size_t)node * F + l * 8 + 4) = w1;
}

// ---------------------------------------------------------------------------
#define POOL_NODES 512
__global__ void k_pool(const float* __restrict__ h, const int* __restrict__ batch,
                       float* __restrict__ sums, float* __restrict__ cnt,
                       int N, int G) {
    __shared__ float sS[MAXG * 32];
    __shared__ float sC[MAXG];
    for (int i = threadIdx.x; i < G * 32; i += 256) sS[i] = 0.0f;
    for (int i = threadIdx.x; i < G; i += 256) sC[i] = 0.0f;
    __syncthreads();

    int f = threadIdx.x % 32;
    int w = threadIdx.x / 32;
    int start = blockIdx.x * POOL_NODES;
    int end = min(start + POOL_NODES, N);
    for (int n = start + w; n < end; n += 8) {
        int g = batch[n];
        atomicAdd(&sS[g * 32 + f], h[(size_t)n * 32 + f]);
        if (f == 0) atomicAdd(&sC[g], 1.0f);
    }
    __syncthreads();

    for (int i = threadIdx.x; i < G * 32; i += 256)
        if (sS[i] != 0.0f) atomicAdd(&sums[i], sS[i]);
    for (int i = threadIdx.x; i < G; i += 256)
        if (sC[i] != 0.0f) atomicAdd(&cnt[i], sC[i]);
}

__global__ void k_final(const float* __restrict__ sums, const float* __restrict__ cnt,
                        float* __restrict__ out, int G) {
    int i = blockIdx.x * blockDim.x + threadIdx.x;
    if (i < G * 32) out[i] = sums[i] / fmaxf(cnt[i / 32], 1.0f);
}

// ---------------------------------------------------------------------------
extern "C" void kernel_launch(void* const* d_in, const int* in_sizes, int n_in,
                              void* d_out, int out_size) {
    const float* x     = (const float*)d_in[0];
    const int*   ei    = (const int*)d_in[1];
    const int*   batch = (const int*)d_in[2];

    int wi = (n_in >= 10) ? 3 : 2;
    const float* W1 = (const float*)d_in[wi + 1];
    const float* b1 = (const float*)d_in[wi + 2];
    const float* W2 = (const float*)d_in[wi + 3];
    const float* b2 = (const float*)d_in[wi + 4];
    const float* W3 = (const float*)d_in[wi + 5];
    const float* b3 = (const float*)d_in[wi + 6];

    int N = in_sizes[0] / 64;
    int E = in_sizes[1] / 2;
    int G = out_size / 32;
    const int* src = ei;
    const int* dst = ei + E;

    float *p_dinv, *p_a, *p_sums, *p_cnt;
    __half *p_h;
    int *p_deg, *p_rowptr, *p_cursor, *p_aux;
    int2 *p_edat;
    cudaGetSymbolAddress((void**)&p_dinv,   g_dinv);
    cudaGetSymbolAddress((void**)&p_deg,    g_deg);
    cudaGetSymbolAddress((void**)&p_rowptr, g_rowptr);
    cudaGetSymbolAddress((void**)&p_cursor, g_cursor);
    cudaGetSymbolAddress((void**)&p_aux,    g_aux);
    cudaGetSymbolAddress((void**)&p_edat,   g_edat);
    cudaGetSymbolAddress((void**)&p_h,      g_h);
    cudaGetSymbolAddress((void**)&p_a,      g_a);
    cudaGetSymbolAddress((void**)&p_sums,   g_sums);
    cudaGetSymbolAddress((void**)&p_cnt,    g_cnt);

    float* out = (float*)d_out;
    const int T = 256;
    int nb_scan = (N + 1023) / 1024;

    // --- build CSC + norms ---
    k_zero<<<(N + T - 1) / T, T>>>(p_deg, p_sums, p_cnt, N, G);
    k_hist<<<(E + T - 1) / T, T>>>(dst, p_deg, E);
    k_dinv<<<(N + T - 1) / T, T>>>(p_deg, p_dinv, N);
    k_scan1<<<nb_scan, 1024>>>(p_deg, p_rowptr, p_aux, N);
    k_scan2<<<1, 128>>>(p_aux, nb_scan);
    k_scan3<<<(N + T - 1) / T, T>>>(p_rowptr, p_cursor, p_aux, N);
    k_scatter<<<(E + T - 1) / T, T>>>(src, dst, p_dinv, p_cursor, p_edat, E);

    // --- layer 1 ---
    k_gemm<64, false><<<(N + 63) / 64, T>>>(x, W1, p_h, N);
    k_agg<64><<<((size_t)N * 8 + T - 1) / T, T>>>(p_h, p_edat, p_rowptr, p_deg,
                                                  p_dinv, b1, p_a, N);
    // --- layer 2 ---
    k_gemm<64, true><<<(N + 63) / 64, T>>>(p_a, W2, p_h, N);
    k_agg<64><<<((size_t)N * 8 + T - 1) / T, T>>>(p_h, p_edat, p_rowptr, p_deg,
                                                  p_dinv, b2, p_a, N);
    // --- layer 3 ---
    k_gemm<32, false><<<(N + 127) / 128, T>>>(p_a, W3, p_h, N);
    k_agg<32><<<((size_t)N * 4 + T - 1) / T, T>>>(p_h, p_edat, p_rowptr, p_deg,
                                                  p_dinv, b3, p_a, N);

    // --- pool ---
    k_pool<<<(N + POOL_NODES - 1) / POOL_NODES, T>>>(p_a, batch, p_sums, p_cnt, N, G);
    k_final<<<(G * 32 + T - 1) / T, T>>>(p_sums, p_cnt, out, G);
}

// round 5
// speedup vs baseline: 2.6579x; 1.0706x over previous
#include <cuda_runtime.h>
#include <cuda_fp16.h>

#define MAXN 100000
#define MAXE 1600000
#define MAXG 64

__device__ __align__(128) float  g_dinv[MAXN];
__device__ __align__(128) int    g_deg[MAXN];
__device__ __align__(128) int    g_rowptr[MAXN];
__device__ __align__(128) int    g_cursor[MAXN];
__device__ __align__(128) int    g_aux[128];
__device__ __align__(128) int    g_esrc[MAXE];      // CSC: src index per slot
__device__ __align__(128) __half g_h[MAXN * 64];    // pre-scaled fp16 features
__device__ __align__(128) float  g_a[MAXN * 64];
__device__ __align__(128) float  g_sums[MAXG * 32];
__device__ __align__(128) float  g_cnt[MAXG];

// ---------------------------------------------------------------------------
__global__ void k_zero(int* deg, float* sums, float* cnt, int N, int G) {
    int i = blockIdx.x * blockDim.x + threadIdx.x;
    if (i < N) deg[i] = 0;
    if (i < G * 32) sums[i] = 0.0f;
    if (i < G) cnt[i] = 0.0f;
}

__global__ void k_hist(const int* __restrict__ dst, int* deg, int E) {
    int e = blockIdx.x * blockDim.x + threadIdx.x;
    if (e < E) atomicAdd(&deg[dst[e]], 1);
}

__global__ void k_dinv(const int* __restrict__ deg, float* dinv, int N) {
    int i = blockIdx.x * blockDim.x + threadIdx.x;
    if (i < N) dinv[i] = rsqrtf((float)deg[i] + 1.0f);  // +1 self loop
}

// --- exclusive scan of deg -> rowptr ---------------------------------------
__global__ void k_scan1(const int* __restrict__ deg, int* rowptr, int* aux, int N) {
    __shared__ int s[1024];
    int i = blockIdx.x * 1024 + threadIdx.x;
    int v = (i < N) ? deg[i] : 0;
    s[threadIdx.x] = v;
    __syncthreads();
    for (int off = 1; off < 1024; off <<= 1) {
        int t = (threadIdx.x >= off) ? s[threadIdx.x - off] : 0;
        __syncthreads();
        s[threadIdx.x] += t;
        __syncthreads();
    }
    if (i < N) rowptr[i] = s[threadIdx.x] - v;
    if (threadIdx.x == 1023) aux[blockIdx.x] = s[1023];
}

__global__ void k_scan2(int* aux, int nb) {
    __shared__ int s[128];
    int v = (threadIdx.x < nb) ? aux[threadIdx.x] : 0;
    s[threadIdx.x] = v;
    __syncthreads();
    for (int off = 1; off < 128; off <<= 1) {
        int t = (threadIdx.x >= off) ? s[threadIdx.x - off] : 0;
        __syncthreads();
        s[threadIdx.x] += t;
        __syncthreads();
    }
    if (threadIdx.x < nb) aux[threadIdx.x] = s[threadIdx.x] - v;
}

__global__ void k_scan3(int* rowptr, int* cursor, const int* __restrict__ aux, int N) {
    int i = blockIdx.x * blockDim.x + threadIdx.x;
    if (i < N) {
        int r = rowptr[i] + aux[i >> 10];
        rowptr[i] = r;
        cursor[i] = r;
    }
}

__global__ void k_scatter(const int* __restrict__ src, const int* __restrict__ dst,
                          int* cursor, int* esrc, int E) {
    int e = blockIdx.x * blockDim.x + threadIdx.x;
    if (e >= E) return;
    int s = src[e], d = dst[e];
    int pos = atomicAdd(&cursor[d], 1);
    esrc[pos] = s;
}

// ---------------------------------------------------------------------------
// Register-blocked GEMM with pre-scale epilogue:
//   h'[N,Fo](fp16) = (act(in)[N,64] @ W[64,Fo]) * dinv[row]
template <int Fo, bool RELU>
__global__ __launch_bounds__(256) void k_gemm(
    const float* __restrict__ in, const float* __restrict__ W,
    const float* __restrict__ dinv, __half* __restrict__ h, int N) {

    constexpr int CG = Fo / 4;
    constexpr int RG = 256 / CG;
    constexpr int RB = RG * 4;

    __shared__ float sX[RB * 64];
    __shared__ float sW[64 * Fo];

    int tid = threadIdx.x;
    for (int i = tid * 4; i < 64 * Fo; i += 1024)
        *(float4*)(sW + i) = *(const float4*)(W + i);

    int r0 = blockIdx.x * RB;
    int nrow = min(RB, N - r0);
    int nflt = nrow * 64;
    const float* gin = in + (size_t)r0 * 64;
    for (int i = tid * 4; i < nflt; i += 1024) {
        float4 v = *(const float4*)(gin + i);
        if (RELU) {
            v.x = fmaxf(v.x, 0.0f); v.y = fmaxf(v.y, 0.0f);
            v.z = fmaxf(v.z, 0.0f); v.w = fmaxf(v.w, 0.0f);
        }
        *(float4*)(sX + i) = v;
    }
    __syncthreads();

    int cx = tid % CG;
    int ry = tid / CG;

    float acc[4][4] = {};
    const float* xs = sX + ry * 4 * 64;
    const float* ws = sW + cx * 4;

#pragma unroll 8
    for (int k = 0; k < 64; k++) {
        float4 wv = *(const float4*)(ws + k * Fo);
        float x0 = xs[k];
        float x1 = xs[64 + k];
        float x2 = xs[128 + k];
        float x3 = xs[192 + k];
        acc[0][0] += x0 * wv.x; acc[0][1] += x0 * wv.y; acc[0][2] += x0 * wv.z; acc[0][3] += x0 * wv.w;
        acc[1][0] += x1 * wv.x; acc[1][1] += x1 * wv.y; acc[1][2] += x1 * wv.z; acc[1][3] += x1 * wv.w;
        acc[2][0] += x2 * wv.x; acc[2][1] += x2 * wv.y; acc[2][2] += x2 * wv.z; acc[2][3] += x2 * wv.w;
        acc[3][0] += x3 * wv.x; acc[3][1] += x3 * wv.y; acc[3][2] += x3 * wv.z; acc[3][3] += x3 * wv.w;
    }

#pragma unroll
    for (int i = 0; i < 4; i++) {
        int gr = r0 + ry * 4 + i;
        if (gr < N) {
            float d = dinv[gr];
            __half2 p0 = __floats2half2_rn(acc[i][0] * d, acc[i][1] * d);
            __half2 p1 = __floats2half2_rn(acc[i][2] * d, acc[i][3] * d);
            uint2 pk = make_uint2(*(unsigned*)&p0, *(unsigned*)&p1);
            *(uint2*)(h + (size_t)gr * Fo + cx * 4) = pk;   // 8B store
        }
    }
}

// ---------------------------------------------------------------------------
// Gather-aggregate (CSC, pre-scaled fp16, fp32 accumulate):
//   out[i] = bias + dinv[i] * ( h'[i] + sum_j h'[src_j] )
// L = F/8 lanes per node; unroll 8 for MLP.
template <int F>
__global__ __launch_bounds__(256) void k_agg(
    const __half* __restrict__ h, const int* __restrict__ esrc,
    const int* __restrict__ rowptr, const int* __restrict__ deg,
    const float* __restrict__ dinv, const float* __restrict__ bias,
    float* __restrict__ out, int N) {

    constexpr int L = F / 8;
    int gid = blockIdx.x * blockDim.x + threadIdx.x;
    int node = gid / L;
    int l = gid % L;
    if (node >= N) return;

    int beg = rowptr[node];
    int cnt = deg[node];

    float acc[8] = {};

    int j = 0;
    for (; j + 7 < cnt; j += 8) {
        int s0 = esrc[beg + j + 0];
        int s1 = esrc[beg + j + 1];
        int s2 = esrc[beg + j + 2];
        int s3 = esrc[beg + j + 3];
        int s4 = esrc[beg + j + 4];
        int s5 = esrc[beg + j + 5];
        int s6 = esrc[beg + j + 6];
        int s7 = esrc[beg + j + 7];
        uint4 r0 = *(const uint4*)(h + (size_t)s0 * F + l * 8);
        uint4 r1 = *(const uint4*)(h + (size_t)s1 * F + l * 8);
        uint4 r2 = *(const uint4*)(h + (size_t)s2 * F + l * 8);
        uint4 r3 = *(const uint4*)(h + (size_t)s3 * F + l * 8);
        uint4 r4 = *(const uint4*)(h + (size_t)s4 * F + l * 8);
        uint4 r5 = *(const uint4*)(h + (size_t)s5 * F + l * 8);
        uint4 r6 = *(const uint4*)(h + (size_t)s6 * F + l * 8);
        uint4 r7 = *(const uint4*)(h + (size_t)s7 * F + l * 8);
        const __half2* p0 = (const __half2*)&r0;
        const __half2* p1 = (const __half2*)&r1;
        const __half2* p2 = (const __half2*)&r2;
        const __half2* p3 = (const __half2*)&r3;
        const __half2* p4 = (const __half2*)&r4;
        const __half2* p5 = (const __half2*)&r5;
        const __half2* p6 = (const __half2*)&r6;
        const __half2* p7 = (const __half2*)&r7;
#pragma unroll
        for (int q = 0; q < 4; q++) {
            float2 f0 = __half22float2(p0[q]);
            float2 f1 = __half22float2(p1[q]);
            float2 f2 = __half22float2(p2[q]);
            float2 f3 = __half22float2(p3[q]);
            float2 f4 = __half22float2(p4[q]);
            float2 f5 = __half22float2(p5[q]);
            float2 f6 = __half22float2(p6[q]);
            float2 f7 = __half22float2(p7[q]);
            acc[2*q]   += ((f0.x + f1.x) + (f2.x + f3.x)) + ((f4.x + f5.x) + (f6.x + f7.x));
            acc[2*q+1] += ((f0.y + f1.y) + (f2.y + f3.y)) + ((f4.y + f5.y) + (f6.y + f7.y));
        }
    }
    for (; j < cnt; j++) {
        int s = esrc[beg + j];
        uint4 r = *(const uint4*)(h + (size_t)s * F + l * 8);
        const __half2* p = (const __half2*)&r;
#pragma unroll
        for (int q = 0; q < 4; q++) {
            float2 f = __half22float2(p[q]);
            acc[2*q]   += f.x;
            acc[2*q+1] += f.y;
        }
    }

    // self term + scale + bias
    float d = dinv[node];
    uint4 rs = *(const uint4*)(h + (size_t)node * F + l * 8);
    const __half2* ps = (const __half2*)&rs;
    float4 b0 = *(const float4*)(bias + l * 8);
    float4 b1 = *(const float4*)(bias + l * 8 + 4);

    float o[8];
#pragma unroll
    for (int q = 0; q < 4; q++) {
        float2 f = __half22float2(ps[q]);
        o[2*q]   = (acc[2*q]   + f.x) * d;
        o[2*q+1] = (acc[2*q+1] + f.y) * d;
    }
    float4 w0 = make_float4(o[0] + b0.x, o[1] + b0.y, o[2] + b0.z, o[3] + b0.w);
    float4 w1 = make_float4(o[4] + b1.x, o[5] + b1.y, o[6] + b1.z, o[7] + b1.w);
    *(float4*)(out + (size_t)node * F + l * 8)     = w0;
    *(float4*)(out + (size_t)node * F + l * 8 + 4) = w1;
}

// ---------------------------------------------------------------------------
#define POOL_NODES 512
__global__ void k_pool(const float* __restrict__ h, const int* __restrict__ batch,
                       float* __restrict__ sums, float* __restrict__ cnt,
                       int N, int G) {
    __shared__ float sS[MAXG * 32];
    __shared__ float sC[MAXG];
    for (int i = threadIdx.x; i < G * 32; i += 256) sS[i] = 0.0f;
    for (int i = threadIdx.x; i < G; i += 256) sC[i] = 0.0f;
    __syncthreads();

    int f = threadIdx.x % 32;
    int w = threadIdx.x / 32;
    int start = blockIdx.x * POOL_NODES;
    int end = min(start + POOL_NODES, N);
    for (int n = start + w; n < end; n += 8) {
        int g = batch[n];
        atomicAdd(&sS[g * 32 + f], h[(size_t)n * 32 + f]);
        if (f == 0) atomicAdd(&sC[g], 1.0f);
    }
    __syncthreads();

    for (int i = threadIdx.x; i < G * 32; i += 256)
        if (sS[i] != 0.0f) atomicAdd(&sums[i], sS[i]);
    for (int i = threadIdx.x; i < G; i += 256)
        if (sC[i] != 0.0f) atomicAdd(&cnt[i], sC[i]);
}

__global__ void k_final(const float* __restrict__ sums, const float* __restrict__ cnt,
                        float* __restrict__ out, int G) {
    int i = blockIdx.x * blockDim.x + threadIdx.x;
    if (i < G * 32) out[i] = sums[i] / fmaxf(cnt[i / 32], 1.0f);
}

// ---------------------------------------------------------------------------
extern "C" void kernel_launch(void* const* d_in, const int* in_sizes, int n_in,
                              void* d_out, int out_size) {
    const float* x     = (const float*)d_in[0];
    const int*   ei    = (const int*)d_in[1];
    const int*   batch = (const int*)d_in[2];

    int wi = (n_in >= 10) ? 3 : 2;
    const float* W1 = (const float*)d_in[wi + 1];
    const float* b1 = (const float*)d_in[wi + 2];
    const float* W2 = (const float*)d_in[wi + 3];
    const float* b2 = (const float*)d_in[wi + 4];
    const float* W3 = (const float*)d_in[wi + 5];
    const float* b3 = (const float*)d_in[wi + 6];

    int N = in_sizes[0] / 64;
    int E = in_sizes[1] / 2;
    int G = out_size / 32;
    const int* src = ei;
    const int* dst = ei + E;

    float *p_dinv, *p_a, *p_sums, *p_cnt;
    __half *p_h;
    int *p_deg, *p_rowptr, *p_cursor, *p_aux, *p_esrc;
    cudaGetSymbolAddress((void**)&p_dinv,   g_dinv);
    cudaGetSymbolAddress((void**)&p_deg,    g_deg);
    cudaGetSymbolAddress((void**)&p_rowptr, g_rowptr);
    cudaGetSymbolAddress((void**)&p_cursor, g_cursor);
    cudaGetSymbolAddress((void**)&p_aux,    g_aux);
    cudaGetSymbolAddress((void**)&p_esrc,   g_esrc);
    cudaGetSymbolAddress((void**)&p_h,      g_h);
    cudaGetSymbolAddress((void**)&p_a,      g_a);
    cudaGetSymbolAddress((void**)&p_sums,   g_sums);
    cudaGetSymbolAddress((void**)&p_cnt,    g_cnt);

    float* out = (float*)d_out;
    const int T = 256;
    int nb_scan = (N + 1023) / 1024;

    // --- build CSC + norms ---
    k_zero<<<(N + T - 1) / T, T>>>(p_deg, p_sums, p_cnt, N, G);
    k_hist<<<(E + T - 1) / T, T>>>(dst, p_deg, E);
    k_dinv<<<(N + T - 1) / T, T>>>(p_deg, p_dinv, N);
    k_scan1<<<nb_scan, 1024>>>(p_deg, p_rowptr, p_aux, N);
    k_scan2<<<1, 128>>>(p_aux, nb_scan);
    k_scan3<<<(N + T - 1) / T, T>>>(p_rowptr, p_cursor, p_aux, N);
    k_scatter<<<(E + T - 1) / T, T>>>(src, dst, p_cursor, p_esrc, E);

    // --- layer 1 ---
    k_gemm<64, false><<<(N + 63) / 64, T>>>(x, W1, p_dinv, p_h, N);
    k_agg<64><<<((size_t)N * 8 + T - 1) / T, T>>>(p_h, p_esrc, p_rowptr, p_deg,
                                                  p_dinv, b1, p_a, N);
    // --- layer 2 ---
    k_gemm<64, true><<<(N + 63) / 64, T>>>(p_a, W2, p_dinv, p_h, N);
    k_agg<64><<<((size_t)N * 8 + T - 1) / T, T>>>(p_h, p_esrc, p_rowptr, p_deg,
                                                  p_dinv, b2, p_a, N);
    // --- layer 3 ---
    k_gemm<32, false><<<(N + 127) / 128, T>>>(p_a, W3, p_dinv, p_h, N);
    k_agg<32><<<((size_t)N * 4 + T - 1) / T, T>>>(p_h, p_esrc, p_rowptr, p_deg,
                                                  p_dinv, b3, p_a, N);

    // --- pool ---
    k_pool<<<(N + POOL_NODES - 1) / POOL_NODES, T>>>(p_a, batch, p_sums, p_cnt, N, G);
    k_final<<<(G * 32 + T - 1) / T, T>>>(p_sums, p_cnt, out, G);
}